// round 17
// baseline (speedup 1.0000x reference)
#include <cuda_runtime.h>
#include <cuda_bf16.h>

// DinoPool == masked average pooling of x over 512-row blocks.
// x: [B=4, S=4096, C=384] fp32 -> out same shape.
// out[b, s, c] = mean_{r in block(s)} x[b, r, c].
//
// FINAL (== R6/R16 champion, best 10.53us, band 10.5-10.8us).
// 384 CTAs x 256 thr, full 148-SM coverage; unit = (bat, blk, 8-float4-col
// chunk); every warp access (load and store) is a full 128B L2 line;
// 16 independent loads/thread cover DRAM latency; smem tree reduction;
// broadcast stores.
//
// 16-round exploration established the floor:
//   - read cap  ~5.1 TB/s (DRAM-side)
//   - write cap ~3.1 TB/s (L2/fabric store path; identical for STG.128,
//     STG.256, TMA bulk; policy- and granularity-independent)
//   - total = ~2.4us exposed read prefix + ~8.1us write stream, with
//     natural CTA spread providing all the overlap that helps.
// Falsified: writer-CTA specialization (R5,R11), warp autonomy (R9),
// fine-grain CTAs (R10), intra-CTA pipelining (R8,R12), cache-policy
// variants (R6/R7/R13), 256-bit ops (R14), front-batch MLP boost (R15).

static constexpr int S       = 4096;
static constexpr int C       = 384;    // H*D
static constexpr int C4      = C / 4;  // 96 float4 per row
static constexpr int BLOCK   = 512;
static constexpr int NBLK    = 8;
static constexpr int NBAT    = 4;
static constexpr int CH4     = 8;          // float4 columns per CTA (128B)
static constexpr int NCH     = C4 / CH4;   // 12 chunks
static constexpr int NT      = 256;
static constexpr int RG      = NT / CH4;   // 32 rowgroups
static constexpr int RPT     = BLOCK / RG; // 16 rows per thread

__global__ __launch_bounds__(NT, 4)
void dinopool_kernel(const float* __restrict__ x, float* __restrict__ out) {
    const int chunk = blockIdx.x;   // 0..11
    const int blk   = blockIdx.y;   // 0..7
    const int bat   = blockIdx.z;   // 0..3

    const int col = threadIdx.x & (CH4 - 1);   // 0..7
    const int rg  = threadIdx.x >> 3;          // 0..31

    const float4* __restrict__ x4 = reinterpret_cast<const float4*>(x);
    float4* __restrict__ o4       = reinterpret_cast<float4*>(out);

    // float4 index of (row rg*RPT, this column) within this (bat, blk)
    const size_t base = ((size_t)bat * S + (size_t)blk * BLOCK
                         + (size_t)rg * RPT) * C4
                        + (size_t)chunk * CH4 + col;

    // ---- accumulate 16 rows per thread (independent loads, high MLP) ----
    float4 acc = make_float4(0.f, 0.f, 0.f, 0.f);
    #pragma unroll
    for (int r = 0; r < RPT; r++) {
        float4 v = __ldcs(&x4[base + (size_t)r * C4]);
        acc.x += v.x; acc.y += v.y; acc.z += v.z; acc.w += v.w;
    }

    // ---- tree reduction across 32 rowgroups in smem ----
    __shared__ float4 sm[RG][CH4];
    sm[rg][col] = acc;
    __syncthreads();
    #pragma unroll
    for (int s = RG / 2; s >= 1; s >>= 1) {
        if (rg < s) {
            float4 a = sm[rg][col];
            float4 b = sm[rg + s][col];
            a.x += b.x; a.y += b.y; a.z += b.z; a.w += b.w;
            sm[rg][col] = a;
        }
        __syncthreads();
    }

    // ---- broadcast mean to this CTA's 512 output rows ----
    float4 mean = sm[0][col];
    const float inv = 1.0f / (float)BLOCK;
    mean.x *= inv; mean.y *= inv; mean.z *= inv; mean.w *= inv;

    #pragma unroll
    for (int r = 0; r < RPT; r++) {
        o4[base + (size_t)r * C4] = mean;
    }
}

extern "C" void kernel_launch(void* const* d_in, const int* in_sizes, int n_in,
                              void* d_out, int out_size) {
    const float* x = (const float*)d_in[0];   // [4, 4096, 384] fp32
    float* out     = (float*)d_out;
    (void)in_sizes; (void)n_in; (void)out_size;

    dim3 grid(NCH /*12*/, NBLK /*8*/, NBAT /*4*/);   // 384 CTAs
    dinopool_kernel<<<grid, NT>>>(x, out);
}